// round 1
// baseline (speedup 1.0000x reference)
#include <cuda_runtime.h>

// Lifting-scheme wavelet forward transform.
// input: (4096, 8192) f32; scaling: (8,) f32; scaling_rec: (8,) f32
// even = input[:, ::2], odd = input[:, 1::2]  (each 4096 wide)
// wavelet[j] = scaling_rec[7-j] * (j odd ? -1 : +1)
// circular 8-tap conv (FFT-equivalent):
//   odd_out[k]  = odd[k]  - sum_j wavelet[j] * even[(k-j) mod 4096]
//   even_out[k] = even[k] - sum_j scaling[j] * odd[(k-j) mod 4096]
// Output: [even_updated (4096x4096) | odd_updated (4096x4096)] flat f32.

#define ROWS      4096
#define ROWLEN    8192
#define HALF      4096
#define NTH       1024
#define MASK      4095

__global__ __launch_bounds__(NTH, 2)
void wavelet_fwd_kernel(const float* __restrict__ in,
                        const float* __restrict__ scaling,
                        const float* __restrict__ scaling_rec,
                        float* __restrict__ out)
{
    __shared__ float sEven[HALF];
    __shared__ float sOdd[HALF];
    __shared__ float fWav[8];
    __shared__ float fScl[8];

    const int row = blockIdx.x;
    const int t   = threadIdx.x;

    if (t < 8) {
        fScl[t] = scaling[t];
        float w = scaling_rec[7 - t];
        fWav[t] = (t & 1) ? -w : w;
    }

    // Coalesced deinterleaving load: each float2 = (even, odd) pair.
    const float2* inrow = reinterpret_cast<const float2*>(in + (size_t)row * ROWLEN);
#pragma unroll
    for (int s = 0; s < HALF / NTH; s++) {
        int i = t + s * NTH;
        float2 v = inrow[i];
        sEven[i] = v.x;
        sOdd[i]  = v.y;
    }
    __syncthreads();

    // Hoist taps to registers (broadcast LDS, no conflicts).
    float w0 = fWav[0], w1 = fWav[1], w2 = fWav[2], w3 = fWav[3];
    float w4 = fWav[4], w5 = fWav[5], w6 = fWav[6], w7 = fWav[7];
    float c0 = fScl[0], c1 = fScl[1], c2 = fScl[2], c3 = fScl[3];
    float c4 = fScl[4], c5 = fScl[5], c6 = fScl[6], c7 = fScl[7];

    float* __restrict__ outE = out + (size_t)row * HALF;
    float* __restrict__ outO = out + (size_t)ROWS * HALF + (size_t)row * HALF;

#pragma unroll
    for (int s = 0; s < HALF / NTH; s++) {
        int k = t + s * NTH;
        // (k - j) & MASK is correct for negative ints (two's complement).
        float ce, co;
        {
            int i0 = k            & MASK;
            int i1 = (k - 1)      & MASK;
            int i2 = (k - 2)      & MASK;
            int i3 = (k - 3)      & MASK;
            int i4 = (k - 4)      & MASK;
            int i5 = (k - 5)      & MASK;
            int i6 = (k - 6)      & MASK;
            int i7 = (k - 7)      & MASK;
            float e0 = sEven[i0], e1 = sEven[i1], e2 = sEven[i2], e3 = sEven[i3];
            float e4 = sEven[i4], e5 = sEven[i5], e6 = sEven[i6], e7 = sEven[i7];
            float o0 = sOdd[i0],  o1 = sOdd[i1],  o2 = sOdd[i2],  o3 = sOdd[i3];
            float o4 = sOdd[i4],  o5 = sOdd[i5],  o6 = sOdd[i6],  o7 = sOdd[i7];
            ce = w0*e0 + w1*e1 + w2*e2 + w3*e3 + w4*e4 + w5*e5 + w6*e6 + w7*e7;
            co = c0*o0 + c1*o1 + c2*o2 + c3*o3 + c4*o4 + c5*o5 + c6*o6 + c7*o7;
            outO[k] = o0 - ce;   // odd[k]  - conv(even, wavelet)[k]
            outE[k] = e0 - co;   // even[k] - conv(odd, scaling)[k]
        }
    }
}

extern "C" void kernel_launch(void* const* d_in, const int* in_sizes, int n_in,
                              void* d_out, int out_size)
{
    const float* input       = (const float*)d_in[0];
    const float* scaling     = (const float*)d_in[1];
    const float* scaling_rec = (const float*)d_in[2];
    float* out = (float*)d_out;

    wavelet_fwd_kernel<<<ROWS, NTH>>>(input, scaling, scaling_rec, out);
}